// round 3
// baseline (speedup 1.0000x reference)
#include <cuda_runtime.h>
#include <cstdint>
#include <cstdio>

// ---------------- problem constants ----------------
#define NP 100000
#define NS 50000
#define PD 1024
#define SD 512
#define HF 64
#define EPN 3200000
#define ESN 1600000
#define ELN 2000000

// ---------------- device scratch (static; zero-initialized at load) ----------------
__device__ float g_bufP0[(size_t)NP * HF];
__device__ float g_bufP1[(size_t)NP * HF];
__device__ float g_bufS0[(size_t)NS * HF];
__device__ float g_bufS1[(size_t)NS * HF];
__device__ float g_dinvP[NP];
__device__ float g_dinvS[NS];
__device__ int   g_rowP[NP + 1];
__device__ int   g_rowS[NS + 1];
__device__ int   g_curP[NP];   // counts -> cursor; MUST be zero at start of each replay
__device__ int   g_curS[NS];
__device__ int   g_srcP[EPN];
__device__ int   g_srcS[ESN];
__device__ float g_Wc[128 * 64 + 64];   // Wcomb [128,64] row-major, then bcomb[64]
__device__ int   g_bsum[256];

// ================= CSR build (both graphs in shared kernels) =================
__global__ void k_countB(const int* __restrict__ eiP, int EP,
                         const int* __restrict__ eiS, int ES,
                         int* __restrict__ cntP, int* __restrict__ cntS) {
    int e = blockIdx.x * blockDim.x + threadIdx.x;
    if (e < EP) {
        atomicAdd(&cntP[eiP[EP + e]], 1);
    } else if (e < EP + ES) {
        int l = e - EP;
        atomicAdd(&cntS[eiS[ES + l]], 1);
    }
}

// per-1024-chunk scan; blocks [0,nbP) cover P, [nbP,nbP+nbS) cover S
__global__ void k_scan1B(const int* __restrict__ cntP, const int* __restrict__ cntS,
                         int* __restrict__ rowP, int* __restrict__ rowS,
                         int* __restrict__ blockSums, int nbP) {
    __shared__ int sh[1024];
    int b = blockIdx.x;
    const int* cnt;
    int* rowOut;
    int N, local0;
    if (b < nbP) { cnt = cntP; rowOut = rowP; N = NP; local0 = b * 1024; }
    else         { cnt = cntS; rowOut = rowS; N = NS; local0 = (b - nbP) * 1024; }
    int i = local0 + threadIdx.x;
    int v = (i < N) ? cnt[i] : 0;
    sh[threadIdx.x] = v;
    __syncthreads();
    for (int off = 1; off < 1024; off <<= 1) {
        int t = 0;
        if ((int)threadIdx.x >= off) t = sh[threadIdx.x - off];
        __syncthreads();
        sh[threadIdx.x] += t;
        __syncthreads();
    }
    int incl = sh[threadIdx.x];
    if (i < N) rowOut[i] = incl - v;          // exclusive within chunk
    if (threadIdx.x == 1023) blockSums[b] = incl;
}

// segmented exclusive scan of blockSums: segment [0,nbP) and [nbP,nbP+nbS)
__global__ void k_scan2B(int* __restrict__ blockSums, int nbP, int nbS) {
    __shared__ int sh[1024];
    int nb = nbP + nbS;
    int t = threadIdx.x;
    int v = (t < nb) ? blockSums[t] : 0;
    sh[t] = v;
    __syncthreads();
    for (int off = 1; off < 1024; off <<= 1) {
        int x = 0;
        if (t >= off) x = sh[t - off];
        __syncthreads();
        sh[t] += x;
        __syncthreads();
    }
    int excl = sh[t] - v;
    int sumP = sh[nbP - 1];
    if (t < nbP) blockSums[t] = excl;
    else if (t < nb) blockSums[t] = excl - sumP;
}

// finalize row offsets + cursor + dinv (fused); also writes row[N] terminators
__global__ void k_scan3B(int* __restrict__ rowP, int* __restrict__ rowS,
                         int* __restrict__ curP, int* __restrict__ curS,
                         const int* __restrict__ blockSums, int nbP,
                         int EP, int ES,
                         float* __restrict__ dinvP, float* __restrict__ dinvS) {
    int i = blockIdx.x * blockDim.x + threadIdx.x;
    if (i < NP) {
        int r = rowP[i] + blockSums[i >> 10];
        int deg = curP[i];                    // count (pre-cursor)
        rowP[i] = r;
        curP[i] = r;
        dinvP[i] = rsqrtf((float)(deg + 1));
        if (i == 0) rowP[NP] = EP;
    } else if (i < NP + NS) {
        int l = i - NP;
        int r = rowS[l] + blockSums[(l >> 10) + nbP];
        int deg = curS[l];
        rowS[l] = r;
        curS[l] = r;
        dinvS[l] = rsqrtf((float)(deg + 1));
        if (l == 0) rowS[NS] = ES;
    }
}

__global__ void k_fillB(const int* __restrict__ eiP, int EP,
                        const int* __restrict__ eiS, int ES,
                        int* __restrict__ curP, int* __restrict__ curS,
                        int* __restrict__ srcP, int* __restrict__ srcS) {
    int e = blockIdx.x * blockDim.x + threadIdx.x;
    if (e < EP) {
        int d = eiP[EP + e];
        int p = atomicAdd(&curP[d], 1);
        srcP[p] = eiP[e];
    } else if (e < EP + ES) {
        int l = e - EP;
        int d = eiS[ES + l];
        int p = atomicAdd(&curS[d], 1);
        srcS[p] = eiS[l];
    }
}

// restore cursor arrays to zero for the next graph replay
__global__ void k_reset(int* __restrict__ curP, int* __restrict__ curS) {
    int i = blockIdx.x * blockDim.x + threadIdx.x;
    if (i < NP) curP[i] = 0;
    if (i < NS) curS[i] = 0;
}

// ========== fp32 GEMM via packed FFMA2: Y[M,64] = X[M,K] @ W[K,64] ==========
#define TM 128
#define TK 16
__global__ __launch_bounds__(256) void k_gemm(const float* __restrict__ X,
                                              const float* __restrict__ W,
                                              float* __restrict__ Y, int M, int K) {
    __shared__ float Xs[TK][TM];   // transposed: Xs[kk][row]
    __shared__ float Ws[TK][HF];

    int tid = threadIdx.x;
    int tx = tid & 15;          // col group: cols tx*4..tx*4+3
    int ty = tid >> 4;          // row group: rows ty*8..ty*8+7
    int row0 = blockIdx.x * TM;
    int c0 = tx * 4;

    // packed accumulators: pa[p][j] = (row ty*8+2p, row ty*8+2p+1) x col c0+j
    unsigned long long pa[4][4];
#pragma unroll
    for (int p = 0; p < 4; p++)
#pragma unroll
        for (int j = 0; j < 4; j++) pa[p][j] = 0ull;

    for (int kt = 0; kt < K; kt += TK) {
        // load X tile: 128 rows x 16 k, 512 float4, 2 per thread, store transposed
#pragma unroll
        for (int l = 0; l < 2; l++) {
            int idx = tid + l * 256;
            int r = idx >> 2;
            int kk4 = (idx & 3) * 4;
            float4 v = make_float4(0.f, 0.f, 0.f, 0.f);
            int gr = row0 + r;
            if (gr < M) v = *(const float4*)(X + (size_t)gr * K + kt + kk4);
            Xs[kk4 + 0][r] = v.x;
            Xs[kk4 + 1][r] = v.y;
            Xs[kk4 + 2][r] = v.z;
            Xs[kk4 + 3][r] = v.w;
        }
        // load W tile: 16 x 64 = 256 float4, 1 per thread
        {
            int kk = tid >> 4;
            int c4 = (tid & 15) * 4;
            *(float4*)&Ws[kk][c4] = *(const float4*)(W + (size_t)(kt + kk) * HF + c4);
        }
        __syncthreads();
#pragma unroll
        for (int kk = 0; kk < TK; kk++) {
            float4 wv = *(const float4*)&Ws[kk][c0];
            unsigned long long wd[4];
            asm("mov.b64 %0, {%1, %1};" : "=l"(wd[0]) : "f"(wv.x));
            asm("mov.b64 %0, {%1, %1};" : "=l"(wd[1]) : "f"(wv.y));
            asm("mov.b64 %0, {%1, %1};" : "=l"(wd[2]) : "f"(wv.z));
            asm("mov.b64 %0, {%1, %1};" : "=l"(wd[3]) : "f"(wv.w));
            float4 xa = *(const float4*)&Xs[kk][ty * 8];
            float4 xb = *(const float4*)&Xs[kk][ty * 8 + 4];
            unsigned long long xp[4];
            asm("mov.b64 %0, {%1, %2};" : "=l"(xp[0]) : "f"(xa.x), "f"(xa.y));
            asm("mov.b64 %0, {%1, %2};" : "=l"(xp[1]) : "f"(xa.z), "f"(xa.w));
            asm("mov.b64 %0, {%1, %2};" : "=l"(xp[2]) : "f"(xb.x), "f"(xb.y));
            asm("mov.b64 %0, {%1, %2};" : "=l"(xp[3]) : "f"(xb.z), "f"(xb.w));
#pragma unroll
            for (int p = 0; p < 4; p++) {
#pragma unroll
                for (int j = 0; j < 4; j++) {
                    asm("fma.rn.f32x2 %0, %1, %2, %0;"
                        : "+l"(pa[p][j]) : "l"(xp[p]), "l"(wd[j]));
                }
            }
        }
        __syncthreads();
    }
    // unpack and store
#pragma unroll
    for (int p = 0; p < 4; p++) {
        float lo[4], hi[4];
#pragma unroll
        for (int j = 0; j < 4; j++)
            asm("mov.b64 {%0, %1}, %2;" : "=f"(lo[j]), "=f"(hi[j]) : "l"(pa[p][j]));
        int gr0 = row0 + ty * 8 + p * 2;
        if (gr0 < M)
            *(float4*)(Y + (size_t)gr0 * HF + c0) = make_float4(lo[0], lo[1], lo[2], lo[3]);
        if (gr0 + 1 < M)
            *(float4*)(Y + (size_t)(gr0 + 1) * HF + c0) = make_float4(hi[0], hi[1], hi[2], hi[3]);
    }
}

// ---------------- GCN aggregation (CSR, warp per dst node) ----------------
// out[dst] = dinv[dst]*( h[dst]*dinv[dst] + sum_src h[src]*dinv[src] ) + bias
__global__ void k_aggregate(const float* __restrict__ H, float* __restrict__ OUT,
                            const int* __restrict__ row, const int* __restrict__ srcs,
                            const float* __restrict__ dinv, const float* __restrict__ bias,
                            int N) {
    int warp = (blockIdx.x * blockDim.x + threadIdx.x) >> 5;
    int lane = threadIdx.x & 31;
    if (warp >= N) return;
    int dst = warp;
    float di = dinv[dst];
    const float2* Hp = (const float2*)H;
    float2 hs = Hp[(size_t)dst * 32 + lane];
    float2 acc = make_float2(hs.x * di, hs.y * di);
    int s = row[dst], e = row[dst + 1];
    for (int base = s; base < e; base += 32) {
        int myIdx = 0;
        float myDs = 0.f;
        if (base + lane < e) {
            myIdx = srcs[base + lane];
            myDs  = dinv[myIdx];
        }
        int n = min(32, e - base);
        for (int t = 0; t < n; t++) {
            int src  = __shfl_sync(0xffffffffu, myIdx, t);
            float ds = __shfl_sync(0xffffffffu, myDs, t);
            float2 h = Hp[(size_t)src * 32 + lane];
            acc.x += h.x * ds;
            acc.y += h.y * ds;
        }
    }
    float2 b2 = ((const float2*)bias)[lane];
    float2 o = make_float2(acc.x * di + b2.x, acc.y * di + b2.y);
    ((float2*)OUT)[(size_t)dst * 32 + lane] = o;
}

// ---------------- fold Wproj/Wl1 into Wcomb, bcomb ----------------
__global__ void k_prepWc(const float* __restrict__ Wproj, const float* __restrict__ bproj,
                         const float* __restrict__ Wl1, const float* __restrict__ bl1,
                         float* __restrict__ Wc) {
    __shared__ float sWl1[128 * 64];
    for (int i = threadIdx.x; i < 128 * 64; i += blockDim.x) sWl1[i] = Wl1[i];
    __syncthreads();
    for (int o = threadIdx.x; o < 128 * 64; o += blockDim.x) {
        int i = o >> 6, j = o & 63;
        float s = 0.f;
        for (int k = 0; k < 128; k++) s += Wproj[i * 128 + k] * sWl1[k * 64 + j];
        Wc[o] = s;
    }
    for (int j = threadIdx.x; j < 64; j += blockDim.x) {
        float s = bl1[j];
        for (int k = 0; k < 128; k++) s += bproj[k] * sWl1[k * 64 + j];
        Wc[128 * 64 + j] = s;
    }
}

// ---------------- link predictor: out[e] = relu(Ap[ep]+As[es]+bc) . wl2 + bl2 ----------------
__global__ void k_link(const float* __restrict__ Ap, const float* __restrict__ As,
                       const int* __restrict__ ep, const int* __restrict__ es,
                       const float* __restrict__ bc, const float* __restrict__ wl2,
                       const float* __restrict__ bl2, float* __restrict__ out, int EL) {
    int warp = (blockIdx.x * blockDim.x + threadIdx.x) >> 5;
    int lane = threadIdx.x & 31;
    if (warp >= EL) return;
    int p = ep[warp];
    int s = es[warp];
    float2 a = ((const float2*)Ap)[(size_t)p * 32 + lane];
    float2 b = ((const float2*)As)[(size_t)s * 32 + lane];
    float2 c = ((const float2*)bc)[lane];
    float hx = fmaxf(a.x + b.x + c.x, 0.f);
    float hy = fmaxf(a.y + b.y + c.y, 0.f);
    float2 w = ((const float2*)wl2)[lane];
    float part = hx * w.x + hy * w.y;
#pragma unroll
    for (int off = 16; off; off >>= 1) part += __shfl_xor_sync(0xffffffffu, part, off);
    if (lane == 0) out[warp] = part + bl2[0];
}

// ---------------- host orchestration ----------------
static inline int cdiv(int a, int b) { return (a + b - 1) / b; }

extern "C" void kernel_launch(void* const* d_in, const int* in_sizes, int n_in,
                              void* d_out, int out_size) {
    const float* x_p  = (const float*)d_in[0];
    const float* x_s  = (const float*)d_in[1];
    const int*   ei_p = (const int*)d_in[2];
    const int*   ei_s = (const int*)d_in[3];
    const int*   ed_p = (const int*)d_in[4];
    const int*   ed_s = (const int*)d_in[5];
    const float* Wp1 = (const float*)d_in[6];
    const float* bp1 = (const float*)d_in[7];
    const float* Ws1 = (const float*)d_in[8];
    const float* bs1 = (const float*)d_in[9];
    const float* Wp2 = (const float*)d_in[10];
    const float* bp2 = (const float*)d_in[11];
    const float* Ws2 = (const float*)d_in[12];
    const float* bs2 = (const float*)d_in[13];
    const float* Wproj = (const float*)d_in[14];
    const float* bproj = (const float*)d_in[15];
    const float* Wl1 = (const float*)d_in[16];
    const float* bl1 = (const float*)d_in[17];
    const float* Wl2 = (const float*)d_in[18];
    const float* bl2 = (const float*)d_in[19];
    float* out = (float*)d_out;

    float *bufP0, *bufP1, *bufS0, *bufS1, *dinvP, *dinvS, *Wc;
    int *rowP, *rowS, *curP, *curS, *srcP, *srcS, *bsum;
    cudaGetSymbolAddress((void**)&bufP0, g_bufP0);
    cudaGetSymbolAddress((void**)&bufP1, g_bufP1);
    cudaGetSymbolAddress((void**)&bufS0, g_bufS0);
    cudaGetSymbolAddress((void**)&bufS1, g_bufS1);
    cudaGetSymbolAddress((void**)&dinvP, g_dinvP);
    cudaGetSymbolAddress((void**)&dinvS, g_dinvS);
    cudaGetSymbolAddress((void**)&rowP,  g_rowP);
    cudaGetSymbolAddress((void**)&rowS,  g_rowS);
    cudaGetSymbolAddress((void**)&curP,  g_curP);
    cudaGetSymbolAddress((void**)&curS,  g_curS);
    cudaGetSymbolAddress((void**)&srcP,  g_srcP);
    cudaGetSymbolAddress((void**)&srcS,  g_srcS);
    cudaGetSymbolAddress((void**)&Wc,    g_Wc);
    cudaGetSymbolAddress((void**)&bsum,  g_bsum);

    const int EP = in_sizes[2] / 2;
    const int ES = in_sizes[3] / 2;
    const int EL = in_sizes[4];
    const int nbP = cdiv(NP, 1024), nbS = cdiv(NS, 1024);

    // ---- CSR build, both graphs (cursor arrays are zero: load-init / k_reset) ----
    k_countB<<<cdiv(EP + ES, 256), 256>>>(ei_p, EP, ei_s, ES, curP, curS);
    k_scan1B<<<nbP + nbS, 1024>>>(curP, curS, rowP, rowS, bsum, nbP);
    k_scan2B<<<1, 1024>>>(bsum, nbP, nbS);
    k_scan3B<<<cdiv(NP + NS, 256), 256>>>(rowP, rowS, curP, curS, bsum, nbP, EP, ES, dinvP, dinvS);
    k_fillB<<<cdiv(EP + ES, 256), 256>>>(ei_p, EP, ei_s, ES, curP, curS, srcP, srcS);

    // ---- big GEMMs early (also: lands in ncu capture window) ----
    k_gemm<<<cdiv(NP, TM), 256>>>(x_p, Wp1, bufP0, NP, PD);
    k_gemm<<<cdiv(NS, TM), 256>>>(x_s, Ws1, bufS0, NS, SD);
    k_prepWc<<<1, 256>>>(Wproj, bproj, Wl1, bl1, Wc);

    // ---- protein GCN ----
    k_aggregate<<<cdiv(NP * 32, 256), 256>>>(bufP0, bufP1, rowP, srcP, dinvP, bp1, NP);
    k_gemm<<<cdiv(NP, TM), 256>>>(bufP1, Wp2, bufP0, NP, HF);
    k_aggregate<<<cdiv(NP * 32, 256), 256>>>(bufP0, bufP1, rowP, srcP, dinvP, bp2, NP);

    // ---- substrate GCN ----
    k_aggregate<<<cdiv(NS * 32, 256), 256>>>(bufS0, bufS1, rowS, srcS, dinvS, bs1, NS);
    k_gemm<<<cdiv(NS, TM), 256>>>(bufS1, Ws2, bufS0, NS, HF);
    k_aggregate<<<cdiv(NS * 32, 256), 256>>>(bufS0, bufS1, rowS, srcS, dinvS, bs2, NS);

    // ---- per-node link features: Ap = z_p @ Wc_top, As = z_s @ Wc_bot ----
    k_gemm<<<cdiv(NP, TM), 256>>>(bufP1, Wc, bufP0, NP, HF);
    k_gemm<<<cdiv(NS, TM), 256>>>(bufS1, Wc + 64 * 64, bufS0, NS, HF);

    // ---- link prediction ----
    {
        long long threads = (long long)EL * 32;
        int blocks = (int)((threads + 255) / 256);
        k_link<<<blocks, 256>>>(bufP0, bufS0, ed_p, ed_s, Wc + 128 * 64, Wl2, bl2, out, EL);
    }

    // ---- restore cursor arrays for next replay ----
    k_reset<<<cdiv(NP, 256), 256>>>(curP, curS);
}